// round 6
// baseline (speedup 1.0000x reference)
#include <cuda_runtime.h>
#include <cuda_bf16.h>

// Problem constants (from reference): B=32, T=512, D=768, dur in [0, 8]
#define LR_B 32
#define LR_T 512
#define LR_D 768
#define GROW 32                 // source rows per scatter block
#define NGRP (LR_T / GROW)      // 16 scatter groups per batch
#define ZROWS 16                // output rows per zero-fill block

// ---------------------------------------------------------------------------
// Single fused kernel.
//
// Scatter blocks (blockIdx.x < NGRP): block (g, b) owns source rows
//   s0 = 32g .. s0+31. Warp 0 recomputes the full per-batch inclusive scan of
//   rounded durations (512 floats from L2, register scan + shfl — ~1% of the
//   block's work), publishes cum[] via smem. Then all 192 threads expand the
//   32 rows: double-buffered x-row loads, `reps` independent float4 streaming
//   stores per row (~128 output rows = 400KB per block).
//
// Zero-fill blocks (blockIdx.x >= NGRP): warp 0 warp-reduces tot[b] from dur,
//   block zeroes its ZROWS output rows where t >= tot (out is 0xAA-poisoned).
//   Most exit immediately after the reduce.
//
// One launch total: no scan kernel, no inter-kernel gap, no global scratch.
// ---------------------------------------------------------------------------
__global__ void __launch_bounds__(192) lr_fused_kernel(
    const float* __restrict__ x,
    const float* __restrict__ dur,
    float* __restrict__ out,
    int t_out)
{
    const int b   = blockIdx.y;
    const int tid = threadIdx.x;
    const int stride4 = LR_D / 4;          // 192 float4 per row
    const float* drow = dur + b * LR_T;

    if (blockIdx.x < NGRP) {
        // ------------------- scatter path -------------------
        __shared__ int sc[GROW + 1];       // sc[r] = exclusive cum before row s0+r
        const int s0 = blockIdx.x * GROW;

        if (tid < 32) {
            const int lane = tid;
            // register scan of 16 rounded durations per lane
            int v[16];
            int run = 0;
            #pragma unroll
            for (int i = 0; i < 16; ++i) {
                float d = __ldg(drow + lane * 16 + i);
                run += (int)floorf(fmaxf(d, 0.0f) + 0.5f);   // identical fp ops to ref
                v[i] = run;
            }
            // exclusive warp-scan of lane totals
            int total = run;
            #pragma unroll
            for (int s = 1; s < 32; s <<= 1) {
                int n = __shfl_up_sync(0xffffffff, total, s);
                if (lane >= s) total += n;
            }
            const int off = total - run;   // exclusive prefix of this lane
            // publish the 33 cum values this block needs:
            // sc[k] = inclusive cum at index s0+k-1 (sc[0] = exclusive before s0)
            #pragma unroll
            for (int i = 0; i < 16; ++i) {
                const int s = lane * 16 + i;           // global source index, scanned value v[i]+off
                const int k = s - s0 + 1;              // slot: cum[s] -> sc[k]
                if (k >= 1 && k <= GROW) sc[k] = v[i] + off;
            }
            if (lane == 0) {
                // sc[0] = cum[s0-1]; lane holding s0-1 is (s0-1)/16 — recompute cheaply:
                // easiest: thread whose range contains s0-1 writes it below; handle s0==0 here.
                if (s0 == 0) sc[0] = 0;
            }
            if (s0 > 0) {
                const int sprev = s0 - 1;
                if (lane == (sprev >> 4)) sc[0] = v[sprev & 15] + off;
            }
        }
        __syncthreads();

        const int prev = sc[0];
        if (sc[GROW] == prev) return;      // whole group empty

        // Expansion with one-row lookahead (double buffer).
        const float4* xbase = (const float4*)(x + ((size_t)b * LR_T + s0) * LR_D) + tid;
        float4* ob = (float4*)(out + (size_t)b * t_out * LR_D) + tid;

        float4 v = __ldg(xbase);           // row s0
        #pragma unroll 4
        for (int r = 0; r < GROW; ++r) {
            // prefetch next row while storing current (independent)
            float4 vn;
            if (r + 1 < GROW) vn = __ldg(xbase + (size_t)(r + 1) * stride4);
            const int lo = sc[r], hi = sc[r + 1];
            for (int t = lo; t < hi; ++t) {
                asm volatile("st.global.cs.v4.f32 [%0], {%1,%2,%3,%4};"
                             :: "l"(ob + (size_t)t * stride4),
                                "f"(v.x), "f"(v.y), "f"(v.z), "f"(v.w) : "memory");
            }
            v = vn;
        }
    } else {
        // ------------------- zero-fill path -------------------
        __shared__ int s_tot;
        if (tid < 32) {
            const int lane = tid;
            int run = 0;
            #pragma unroll
            for (int i = 0; i < 16; ++i) {
                float d = __ldg(drow + lane * 16 + i);
                run += (int)floorf(fmaxf(d, 0.0f) + 0.5f);
            }
            #pragma unroll
            for (int s = 16; s >= 1; s >>= 1)
                run += __shfl_xor_sync(0xffffffff, run, s);
            if (lane == 0) s_tot = run;
        }
        __syncthreads();

        const int tot = s_tot;
        const int t0  = (blockIdx.x - NGRP) * ZROWS;
        if (t0 + ZROWS <= tot) return;     // fully inside valid region

        const float4 z = make_float4(0.f, 0.f, 0.f, 0.f);
        float4* ob = (float4*)(out + (size_t)b * t_out * LR_D) + tid;
        #pragma unroll
        for (int r = 0; r < ZROWS; ++r) {
            const int t = t0 + r;
            if (t >= tot && t < t_out) {
                asm volatile("st.global.cs.v4.f32 [%0], {%1,%2,%3,%4};"
                             :: "l"(ob + (size_t)t * stride4),
                                "f"(z.x), "f"(z.y), "f"(z.z), "f"(z.w) : "memory");
            }
        }
    }
}

// ---------------------------------------------------------------------------
extern "C" void kernel_launch(void* const* d_in, const int* in_sizes, int n_in,
                              void* d_out, int out_size) {
    const float* x   = (const float*)d_in[0];   // [B, T, D] f32
    const float* dur = (const float*)d_in[1];   // [B, T]    f32
    float* out = (float*)d_out;                 // [B, t_out, D] f32

    const int t_out = out_size / (LR_B * LR_D);
    const int zero_blocks = (t_out + ZROWS - 1) / ZROWS;

    dim3 grid(NGRP + zero_blocks, LR_B);
    lr_fused_kernel<<<grid, 192>>>(x, dur, out, t_out);
}

// round 7
// speedup vs baseline: 1.6932x; 1.6932x over previous
#include <cuda_runtime.h>
#include <cuda_bf16.h>

// Problem constants (from reference): B=32, T=512, D=768
#define LR_B 32
#define LR_T 512
#define LR_D 768
#define ZROWS 8   // output rows handled per zero-fill block

// Scratch (no cudaMalloc allowed): per-batch inclusive cumsum + totals
__device__ int g_cum[LR_B * LR_T];
__device__ int g_tot[LR_B];

// ---------------------------------------------------------------------------
// Kernel 1: per-batch rounded-duration inclusive scan.
// One warp per batch: register scan of 16 elems/lane + shfl scan of lane
// totals. No __syncthreads. ~2us for all 32 batches.
// ---------------------------------------------------------------------------
__global__ void __launch_bounds__(32) lr_scan_kernel(const float* __restrict__ dur) {
    const int b = blockIdx.x;
    const int lane = threadIdx.x;
    const int base = b * LR_T + lane * 16;

    int v[16];
    int run = 0;
    #pragma unroll
    for (int i = 0; i < 16; ++i) {
        float d = __ldg(dur + base + i);
        run += (int)floorf(fmaxf(d, 0.0f) + 0.5f);   // identical fp ops to reference
        v[i] = run;
    }

    int total = run;
    #pragma unroll
    for (int s = 1; s < 32; s <<= 1) {
        int n = __shfl_up_sync(0xffffffff, total, s);
        if (lane >= s) total += n;
    }
    const int off = total - run;   // exclusive prefix for this lane

    #pragma unroll
    for (int i = 0; i < 16; ++i) g_cum[base + i] = v[i] + off;
    if (lane == 31) g_tot[b] = v[15] + off;
}

// ---------------------------------------------------------------------------
// Kernel 2: scatter/expand + tail zero-fill (R3 structure — best measured).
// Launched with PDL: blocks may start while the scan kernel is still running.
// The x-row load address depends only on blockIdx, so issue it BEFORE
// cudaGridDependencySynchronize(); read g_cum/g_tot only after.
// ---------------------------------------------------------------------------
__global__ void __launch_bounds__(192) lr_expand_kernel(
    const float* __restrict__ x,
    float* __restrict__ out,
    int t_out)
{
    const int b   = blockIdx.y;
    const int tid = threadIdx.x;
    const int stride4 = LR_D / 4;   // 192 float4 per row

    if (blockIdx.x < LR_T) {
        // ---- scatter path ----
        const int s = blockIdx.x;

        // Issue the source-row load first (independent of the scan's output).
        const float4* xq = (const float4*)(x + ((size_t)b * LR_T + s) * LR_D) + tid;
        float4 v;
        asm volatile("ld.global.cs.v4.f32 {%0,%1,%2,%3}, [%4];"
                     : "=f"(v.x), "=f"(v.y), "=f"(v.z), "=f"(v.w)
                     : "l"(xq));

        // Now wait for the scan kernel's writes to be visible.
        cudaGridDependencySynchronize();

        const int cs   = g_cum[b * LR_T + s];
        const int prev = (s == 0) ? 0 : g_cum[b * LR_T + s - 1];
        const int reps = cs - prev;
        if (reps == 0) return;

        float4* obase = (float4*)(out + ((size_t)b * t_out + prev) * LR_D) + tid;

        #pragma unroll 4
        for (int r = 0; r < reps; ++r) {
            asm volatile("st.global.cs.v4.f32 [%0], {%1,%2,%3,%4};"
                         :: "l"(obase + (size_t)r * stride4),
                            "f"(v.x), "f"(v.y), "f"(v.z), "f"(v.w)
                         : "memory");
        }
    } else {
        // ---- zero-fill path ----
        cudaGridDependencySynchronize();

        const int tot = g_tot[b];
        const int t0  = (blockIdx.x - LR_T) * ZROWS;
        if (t0 + ZROWS <= tot) return;  // fully inside valid region

        const float4 z = make_float4(0.f, 0.f, 0.f, 0.f);
        float4* ob = (float4*)(out + (size_t)b * t_out * LR_D) + tid;
        #pragma unroll
        for (int r = 0; r < ZROWS; ++r) {
            const int t = t0 + r;
            if (t >= tot && t < t_out) {
                asm volatile("st.global.cs.v4.f32 [%0], {%1,%2,%3,%4};"
                             :: "l"(ob + (size_t)t * stride4),
                                "f"(z.x), "f"(z.y), "f"(z.z), "f"(z.w)
                             : "memory");
            }
        }
    }
}

// ---------------------------------------------------------------------------
extern "C" void kernel_launch(void* const* d_in, const int* in_sizes, int n_in,
                              void* d_out, int out_size) {
    const float* x   = (const float*)d_in[0];   // [B, T, D] f32
    const float* dur = (const float*)d_in[1];   // [B, T]    f32
    float* out = (float*)d_out;                 // [B, t_out, D] f32

    const int t_out = out_size / (LR_B * LR_D);

    lr_scan_kernel<<<LR_B, 32>>>(dur);

    // Expand kernel with programmatic dependent launch: overlaps its ramp-up
    // (and the x-row loads) with the tail of the scan kernel.
    const int zero_blocks = (t_out + ZROWS - 1) / ZROWS;
    cudaLaunchConfig_t cfg = {};
    cfg.gridDim  = dim3(LR_T + zero_blocks, LR_B, 1);
    cfg.blockDim = dim3(192, 1, 1);
    cfg.dynamicSmemBytes = 0;
    cfg.stream = 0;  // capture stream (legacy default)

    cudaLaunchAttribute attr[1];
    attr[0].id = cudaLaunchAttributeProgrammaticStreamSerialization;
    attr[0].val.programmaticStreamSerializationAllowed = 1;
    cfg.attrs = attr;
    cfg.numAttrs = 1;

    cudaLaunchKernelEx(&cfg, lr_expand_kernel, x, out, t_out);
}